// round 13
// baseline (speedup 1.0000x reference)
#include <cuda_runtime.h>
#include <cuda_fp16.h>
#include <stdint.h>
#include <math.h>

#define B_    2
#define S_    2048
#define H_    1024
#define G_    4
#define HPG_  4
#define HD_   64
#define M_    (B_ * S_)          // 4096
#define NHEADS (B_ * G_ * HPG_)  // 32
#define NW_   (H_ * H_)          // 1M elems per weight

// ---------------- scratch (device globals; no allocation allowed) ----------
__device__ __half g_xf[M_ * H_];        // x fp16
__device__ __half g_wf[4 * H_ * H_];    // Wq|Wk|Wv|Wo fp16 (contiguous)
__device__ __half g_cf[M_ * H_];        // ctx fp16, [b*S+s][gh*64+hd]
__device__ __half g_qf[M_ * H_];        // q/k/v fp16, [hidx][s][hd]
__device__ __half g_kf[M_ * H_];
__device__ __half g_vf[M_ * H_];

// ---------------- PTX helpers (plain sm_80/90 features only) ----------------
__device__ __forceinline__ uint32_t smem_u32(const void* p) {
    uint32_t a;
    asm("{ .reg .u64 t; cvta.to.shared.u64 t, %1; cvt.u32.u64 %0, t; }" : "=r"(a) : "l"(p));
    return a;
}
__device__ __forceinline__ void cp16(uint32_t dst, const void* src) {
    asm volatile("cp.async.cg.shared.global [%0], [%1], 16;" :: "r"(dst), "l"(src) : "memory");
}
#define CP_COMMIT() asm volatile("cp.async.commit_group;" ::: "memory")
#define CP_WAIT1()  asm volatile("cp.async.wait_group 1;" ::: "memory")
#define LDSM4(r, a) \
    asm volatile("ldmatrix.sync.aligned.m8n8.x4.shared.b16 {%0,%1,%2,%3}, [%4];" \
        : "=r"((r)[0]), "=r"((r)[1]), "=r"((r)[2]), "=r"((r)[3]) : "r"(a))
#define LDSM4T(r, a) \
    asm volatile("ldmatrix.sync.aligned.m8n8.x4.trans.shared.b16 {%0,%1,%2,%3}, [%4];" \
        : "=r"((r)[0]), "=r"((r)[1]), "=r"((r)[2]), "=r"((r)[3]) : "r"(a))
#define MMA_FP16(d, a, b0, b1) \
    asm volatile("mma.sync.aligned.m16n8k16.row.col.f32.f16.f16.f32 " \
        "{%0,%1,%2,%3}, {%4,%5,%6,%7}, {%8,%9}, {%0,%1,%2,%3};" \
        : "+f"((d)[0]), "+f"((d)[1]), "+f"((d)[2]), "+f"((d)[3]) \
        : "r"((a)[0]), "r"((a)[1]), "r"((a)[2]), "r"((a)[3]), "r"(b0), "r"(b1))

__device__ __forceinline__ uint32_t packh(float hi, float lo) {
    uint32_t d;
    asm("cvt.rn.f16x2.f32 %0, %1, %2;" : "=r"(d) : "f"(hi), "f"(lo));
    return d;
}

// smem row swizzle: 128B rows, 16B chunk q of row r at r*128 + ((q^(r&7))<<4)
#define SW(r, q) ((uint32_t)(r) * 128u + (uint32_t)((((q) ^ ((r) & 7)) << 4)))

// ---------------------------------------------------------------------------
// fused convert fp32 -> fp16 for x + 4 weights (one launch)
// ---------------------------------------------------------------------------
__global__ void __launch_bounds__(256) conv_all(
    const float* __restrict__ x,
    const float* __restrict__ Wq, const float* __restrict__ Wk,
    const float* __restrict__ Wv, const float* __restrict__ Wo,
    __half* __restrict__ xf, __half* __restrict__ wf)
{
    int blk = blockIdx.x;
    const float* src;
    __half* dst;
    int off;
    if (blk < 4096) {
        src = x; dst = xf; off = blk;
    } else {
        int w = (blk - 4096) >> 10;
        off = (blk - 4096) & 1023;
        src = (w == 0) ? Wq : (w == 1) ? Wk : (w == 2) ? Wv : Wo;
        dst = wf + (size_t)w * NW_;
    }
    int i = off * 1024 + threadIdx.x * 4;
    float4 v = *(const float4*)(src + i);
    *(uint32_t*)(dst + i)     = packh(v.y, v.x);
    *(uint32_t*)(dst + i + 2) = packh(v.w, v.z);
}

// ---------------------------------------------------------------------------
// fp16 GEMM core, BK=64, 128B-row swizzle (attention-proven layout).
// CTA 128x128, 8 warps (4m x 2n), 3-stage cp.async pipeline (32KB/stage),
// 16 iterations, one __syncthreads per iteration. 2 CTAs/SM (reg-capped).
// GEMM_BODY computes acc[2][8][4]; caller supplies epilogue.
// ---------------------------------------------------------------------------
#define GEMM_STAGE 32768
#define GEMM_SMEM  (3 * GEMM_STAGE)

#define GEMM_BODY(Aptr, Wptr) \
    uint32_t sbase = smem_u32(smdyn); \
    int tid  = threadIdx.x; \
    int wid  = tid >> 5, lane = tid & 31; \
    int warp_m = wid & 3, warp_n = wid >> 2; \
    int lr = tid >> 1, lqb = (tid & 1) * 4; \
    const char* gA = (const char*)((Aptr) + (size_t)(bm + lr) * 1024); \
    const char* gW = (const char*)((Wptr) + (size_t)(bn + lr) * 1024); \
    int mat = lane >> 3, l7 = lane & 7; \
    int aRow0 = warp_m * 32 + (mat & 1) * 8 + l7; \
    int bRow0 = warp_n * 64 + (mat >> 1) * 8 + l7; \
    float acc[2][8][4]; \
    _Pragma("unroll") \
    for (int mt = 0; mt < 2; mt++) \
        _Pragma("unroll") \
        for (int nt = 0; nt < 8; nt++) \
            _Pragma("unroll") \
            for (int j = 0; j < 4; j++) acc[mt][nt][j] = 0.f; \
    ISSUE_G(0); \
    ISSUE_G(1); \
    for (int c = 0; c < 16; c++) { \
        CP_WAIT1(); \
        __syncthreads(); \
        if (c + 2 < 16) ISSUE_G(c + 2); \
        uint32_t st = sbase + (uint32_t)((c % 3) * GEMM_STAGE); \
        _Pragma("unroll") \
        for (int kc = 0; kc < 4; kc++) { \
            uint32_t Af[2][4], Bf[4][4]; \
            int qa = kc * 2 + (mat >> 1); \
            int qb = kc * 2 + (mat & 1); \
            LDSM4(Af[0], st + SW(aRow0, qa)); \
            LDSM4(Af[1], st + SW(aRow0 + 16, qa)); \
            _Pragma("unroll") \
            for (int g4 = 0; g4 < 4; g4++) \
                LDSM4(Bf[g4], st + 16384 + SW(bRow0 + g4 * 16, qb)); \
            _Pragma("unroll") \
            for (int mt = 0; mt < 2; mt++) \
                _Pragma("unroll") \
                for (int nt = 0; nt < 8; nt++) \
                    MMA_FP16(acc[mt][nt], Af[mt], \
                             Bf[nt >> 1][(nt & 1) * 2], Bf[nt >> 1][(nt & 1) * 2 + 1]); \
        } \
    }

#define ISSUE_G(slab) do { \
    uint32_t st_ = sbase + (uint32_t)(((slab) % 3) * GEMM_STAGE); \
    size_t go_ = (size_t)(slab) * 128; \
    _Pragma("unroll") \
    for (int i_ = 0; i_ < 4; i_++) { \
        uint32_t sw_ = SW(lr, lqb + i_); \
        cp16(st_ + sw_,         gA + go_ + (lqb + i_) * 16); \
        cp16(st_ + 16384 + sw_, gW + go_ + (lqb + i_) * 16); \
    } \
    CP_COMMIT(); \
} while (0)

// ---------------------------------------------------------------------------
// Merged QKV GEMM: grid (24, 32), head-remap fp16 epilogue.
// ---------------------------------------------------------------------------
__global__ void __launch_bounds__(256, 2) tc_gemm_qkv(
    const __half* __restrict__ A, const __half* __restrict__ Wbase,
    const float* __restrict__ bq, const float* __restrict__ bk,
    const float* __restrict__ bv,
    __half* __restrict__ Qo, __half* __restrict__ Ko, __half* __restrict__ Vo)
{
    extern __shared__ __align__(128) char smdyn[];
    int bm = blockIdx.y * 128, bn = blockIdx.x * 128;   // bn in [0,3072)
    int which = bn >> 10;                               // 0=q 1=k 2=v
    const float* bias = (which == 0) ? bq : (which == 1) ? bk : bv;
    __half* Out = (which == 0) ? Qo : (which == 1) ? Ko : Vo;

    GEMM_BODY(A, Wbase)

    int g = lane >> 2, t = lane & 3;
#pragma unroll
    for (int mt = 0; mt < 2; mt++) {
        int row0 = bm + warp_m * 32 + mt * 16 + g;
#pragma unroll
        for (int nt = 0; nt < 8; nt++) {
            int col = bn + warp_n * 64 + nt * 8 + 2 * t;
            int inner = col & 1023;
            float2 bvv = *(const float2*)(bias + inner);
            float v0 = acc[mt][nt][0] + bvv.x, v1 = acc[mt][nt][1] + bvv.y;
            float v2 = acc[mt][nt][2] + bvv.x, v3 = acc[mt][nt][3] + bvv.y;
            int gph = inner >> 6, hd0 = inner & 63;
            int b0 = row0 >> 11, s0 = row0 & 2047;
            int b1 = (row0 + 8) >> 11, s1 = (row0 + 8) & 2047;
            size_t i0 = (size_t)(b0 * 16 + gph) * (S_ * HD_) + (size_t)s0 * HD_ + hd0;
            size_t i1 = (size_t)(b1 * 16 + gph) * (S_ * HD_) + (size_t)s1 * HD_ + hd0;
            *(uint32_t*)(Out + i0) = packh(v1, v0);
            *(uint32_t*)(Out + i1) = packh(v3, v2);
        }
    }
}

// ---------------------------------------------------------------------------
// Wo GEMM: grid (8, 32), fp32 row-major epilogue.
// ---------------------------------------------------------------------------
__global__ void __launch_bounds__(256, 2) tc_gemm_wo(
    const __half* __restrict__ A, const __half* __restrict__ W,
    const float* __restrict__ bias, float* __restrict__ C)
{
    extern __shared__ __align__(128) char smdyn[];
    int bm = blockIdx.y * 128, bn = blockIdx.x * 128;

    GEMM_BODY(A, W)

    int g = lane >> 2, t = lane & 3;
#pragma unroll
    for (int mt = 0; mt < 2; mt++) {
        int row0 = bm + warp_m * 32 + mt * 16 + g;
#pragma unroll
        for (int nt = 0; nt < 8; nt++) {
            int col = bn + warp_n * 64 + nt * 8 + 2 * t;
            float2 bvv = *(const float2*)(bias + col);
            *(float2*)(C + (size_t)row0 * H_ + col) =
                make_float2(acc[mt][nt][0] + bvv.x, acc[mt][nt][1] + bvv.y);
            *(float2*)(C + (size_t)(row0 + 8) * H_ + col) =
                make_float2(acc[mt][nt][2] + bvv.x, acc[mt][nt][3] + bvv.y);
        }
    }
}
#undef ISSUE_G

// ---------------------------------------------------------------------------
// Single-term fp16 flash attention (unchanged from R12; 2 CTAs/SM).
// ---------------------------------------------------------------------------
__global__ void __launch_bounds__(256, 2) attn_fp16(
    const __half* __restrict__ Qf, const __half* __restrict__ Kf,
    const __half* __restrict__ Vf, __half* __restrict__ Cf)
{
    extern __shared__ __align__(128) char smdyn[];   // 3 stages x 16KB
    uint32_t s0 = smem_u32(smdyn);

    int hidx = blockIdx.y, qt = blockIdx.x;
    int tid = threadIdx.x, warp = tid >> 5, lane = tid & 31;
    int g = lane >> 2, t = lane & 3;
    int mat = lane >> 3, l7 = lane & 7;

    size_t hoff = (size_t)hidx * (S_ * HD_);
    const char* Qg = (const char*)(Qf + hoff + (size_t)qt * 128 * HD_);
    const char* Kg = (const char*)(Kf + hoff);
    const char* Vg = (const char*)(Vf + hoff);

    {
        int r = tid >> 1, qb = (tid & 1) * 4;
#pragma unroll
        for (int i = 0; i < 4; i++)
            cp16(s0 + SW(r, qb + i), Qg + (size_t)r * 128 + (qb + i) * 16);
        CP_COMMIT();
        asm volatile("cp.async.wait_group 0;" ::: "memory");
        __syncthreads();
    }
    uint32_t qf[4][4];
    {
        int aRow = warp * 16 + (mat & 1) * 8 + l7;
#pragma unroll
        for (int kc = 0; kc < 4; kc++) {
            int q = kc * 2 + (mat >> 1);
            LDSM4(qf[kc], s0 + SW(aRow, q));
        }
    }
    __syncthreads();

    int kr = tid >> 2, kqb = (tid & 3) * 2;
#define ISSUE_KV(kt) do { \
    uint32_t st_ = s0 + (uint32_t)(((kt) % 3) * 16384); \
    size_t ro_ = (size_t)((kt) * 64 + kr) * 128; \
    _Pragma("unroll") \
    for (int j_ = 0; j_ < 2; j_++) { \
        int q_ = kqb + j_; \
        uint32_t sw_ = SW(kr, q_); \
        cp16(st_ + 0    + sw_, Kg + ro_ + q_ * 16); \
        cp16(st_ + 8192 + sw_, Vg + ro_ + q_ * 16); \
    } \
    CP_COMMIT(); \
} while (0)

    float oacc[8][4];
#pragma unroll
    for (int j = 0; j < 8; j++)
#pragma unroll
        for (int i = 0; i < 4; i++) oacc[j][i] = 0.f;
    float m0 = -1e30f, m1 = -1e30f, l0 = 0.f, l1 = 0.f;
    const float SC = 0.18033688011112042f;   // (1/sqrt(64)) * log2(e)

    ISSUE_KV(0);
    ISSUE_KV(1);

    for (int kt = 0; kt < 32; kt++) {
        CP_WAIT1();
        __syncthreads();
        if (kt + 2 < 32) ISSUE_KV(kt + 2);
        uint32_t st = s0 + (uint32_t)((kt % 3) * 16384);

        float sacc[8][4];
#pragma unroll
        for (int j = 0; j < 8; j++)
#pragma unroll
            for (int i = 0; i < 4; i++) sacc[j][i] = 0.f;

#pragma unroll
        for (int nc = 0; nc < 4; nc++) {
            uint32_t kf[4][4];
            int bRow = nc * 16 + (mat >> 1) * 8 + l7;
#pragma unroll
            for (int kc = 0; kc < 4; kc++) {
                int q = kc * 2 + (mat & 1);
                LDSM4(kf[kc], st + SW(bRow, q));
            }
#pragma unroll
            for (int kc = 0; kc < 4; kc++) {
                MMA_FP16(sacc[2 * nc],     qf[kc], kf[kc][0], kf[kc][1]);
                MMA_FP16(sacc[2 * nc + 1], qf[kc], kf[kc][2], kf[kc][3]);
            }
        }

        float tm0 = -1e30f, tm1 = -1e30f;
#pragma unroll
        for (int j = 0; j < 8; j++) {
            tm0 = fmaxf(tm0, fmaxf(sacc[j][0], sacc[j][1]));
            tm1 = fmaxf(tm1, fmaxf(sacc[j][2], sacc[j][3]));
        }
        tm0 *= SC; tm1 *= SC;
        tm0 = fmaxf(tm0, __shfl_xor_sync(0xFFFFFFFFu, tm0, 1));
        tm0 = fmaxf(tm0, __shfl_xor_sync(0xFFFFFFFFu, tm0, 2));
        tm1 = fmaxf(tm1, __shfl_xor_sync(0xFFFFFFFFu, tm1, 1));
        tm1 = fmaxf(tm1, __shfl_xor_sync(0xFFFFFFFFu, tm1, 2));
        float nm0 = fmaxf(m0, tm0), nm1 = fmaxf(m1, tm1);
        float sc0 = exp2f(m0 - nm0), sc1 = exp2f(m1 - nm1);
        m0 = nm0; m1 = nm1;

        uint32_t pa[4][4];
        float sum0 = 0.f, sum1 = 0.f;
#pragma unroll
        for (int kc = 0; kc < 4; kc++) {
            int j0 = 2 * kc, j1 = 2 * kc + 1;
            float p00 = exp2f(sacc[j0][0] * SC - nm0);
            float p01 = exp2f(sacc[j0][1] * SC - nm0);
            float p02 = exp2f(sacc[j0][2] * SC - nm1);
            float p03 = exp2f(sacc[j0][3] * SC - nm1);
            float p10 = exp2f(sacc[j1][0] * SC - nm0);
            float p11 = exp2f(sacc[j1][1] * SC - nm0);
            float p12 = exp2f(sacc[j1][2] * SC - nm1);
            float p13 = exp2f(sacc[j1][3] * SC - nm1);
            sum0 += (p00 + p01) + (p10 + p11);
            sum1 += (p02 + p03) + (p12 + p13);
            pa[kc][0] = packh(p01, p00);
            pa[kc][1] = packh(p03, p02);
            pa[kc][2] = packh(p11, p10);
            pa[kc][3] = packh(p13, p12);
        }
        sum0 += __shfl_xor_sync(0xFFFFFFFFu, sum0, 1);
        sum0 += __shfl_xor_sync(0xFFFFFFFFu, sum0, 2);
        sum1 += __shfl_xor_sync(0xFFFFFFFFu, sum1, 1);
        sum1 += __shfl_xor_sync(0xFFFFFFFFu, sum1, 2);
        l0 = l0 * sc0 + sum0;
        l1 = l1 * sc1 + sum1;
#pragma unroll
        for (int j = 0; j < 8; j++) {
            oacc[j][0] *= sc0; oacc[j][1] *= sc0;
            oacc[j][2] *= sc1; oacc[j][3] *= sc1;
        }

#pragma unroll
        for (int nc2 = 0; nc2 < 4; nc2++) {
            uint32_t vf[4][4];
#pragma unroll
            for (int kc = 0; kc < 4; kc++) {
                int vRow = kc * 16 + (mat & 1) * 8 + l7;
                int q = nc2 * 2 + (mat >> 1);
                LDSM4T(vf[kc], st + 8192 + SW(vRow, q));
            }
#pragma unroll
            for (int kc = 0; kc < 4; kc++) {
                MMA_FP16(oacc[2 * nc2],     pa[kc], vf[kc][0], vf[kc][1]);
                MMA_FP16(oacc[2 * nc2 + 1], pa[kc], vf[kc][2], vf[kc][3]);
            }
        }
    }
#undef ISSUE_KV

    float inv0 = 1.f / l0, inv1 = 1.f / l1;
    int b  = hidx >> 4, gh = hidx & 15;
    int srow = qt * 128 + warp * 16 + g;
    size_t base0 = ((size_t)b * S_ + srow) * H_ + gh * 64 + 2 * t;
    size_t base1 = base0 + 8 * (size_t)H_;
#pragma unroll
    for (int j = 0; j < 8; j++) {
        float v0 = oacc[j][0] * inv0, v1 = oacc[j][1] * inv0;
        float v2 = oacc[j][2] * inv1, v3 = oacc[j][3] * inv1;
        *(uint32_t*)(Cf + base0 + j * 8) = packh(v1, v0);
        *(uint32_t*)(Cf + base1 + j * 8) = packh(v3, v2);
    }
}

// ---------------------------------------------------------------------------
extern "C" void kernel_launch(void* const* d_in, const int* in_sizes, int n_in,
                              void* d_out, int out_size)
{
    const float* x  = (const float*)d_in[0];
    const float* Wq = (const float*)d_in[1];
    const float* bq = (const float*)d_in[2];
    const float* Wk = (const float*)d_in[3];
    const float* bk = (const float*)d_in[4];
    const float* Wv = (const float*)d_in[5];
    const float* bv = (const float*)d_in[6];
    const float* Wo = (const float*)d_in[7];
    const float* bo = (const float*)d_in[8];
    float* out = (float*)d_out;

    __half *xf, *wf, *cf, *qf, *kf, *vf;
    cudaGetSymbolAddress((void**)&xf, g_xf);
    cudaGetSymbolAddress((void**)&wf, g_wf);
    cudaGetSymbolAddress((void**)&cf, g_cf);
    cudaGetSymbolAddress((void**)&qf, g_qf);
    cudaGetSymbolAddress((void**)&kf, g_kf);
    cudaGetSymbolAddress((void**)&vf, g_vf);

    cudaFuncSetAttribute(attn_fp16,   cudaFuncAttributeMaxDynamicSharedMemorySize, 49152);
    cudaFuncSetAttribute(tc_gemm_qkv, cudaFuncAttributeMaxDynamicSharedMemorySize, GEMM_SMEM);
    cudaFuncSetAttribute(tc_gemm_wo,  cudaFuncAttributeMaxDynamicSharedMemorySize, GEMM_SMEM);

    conv_all<<<8192, 256>>>(x, Wq, Wk, Wv, Wo, xf, wf);

    tc_gemm_qkv<<<dim3(24, 32), 256, GEMM_SMEM>>>(xf, wf, bq, bk, bv, qf, kf, vf);

    attn_fp16<<<dim3(16, 32), 256, 49152>>>(qf, kf, vf, cf);

    tc_gemm_wo<<<dim3(8, 32), 256, GEMM_SMEM>>>(cf, wf + 3 * NW_, bo, out);
}

// round 15
// speedup vs baseline: 1.0515x; 1.0515x over previous
#include <cuda_runtime.h>
#include <cuda_fp16.h>
#include <stdint.h>
#include <math.h>

#define B_    2
#define S_    2048
#define H_    1024
#define G_    4
#define HPG_  4
#define HD_   64
#define M_    (B_ * S_)          // 4096
#define NHEADS (B_ * G_ * HPG_)  // 32
#define NW_   (H_ * H_)          // 1M elems per weight

// ---------------- scratch (device globals; no allocation allowed) ----------
__device__ __half g_xf[M_ * H_];        // x fp16
__device__ __half g_wf[4 * H_ * H_];    // Wq|Wk|Wv|Wo fp16 (contiguous)
__device__ __half g_cf[M_ * H_];        // ctx fp16, [b*S+s][gh*64+hd]
__device__ __half g_qf[M_ * H_];        // q/k/v fp16, [hidx][s][hd]
__device__ __half g_kf[M_ * H_];
__device__ __half g_vf[M_ * H_];

// ---------------- PTX helpers (plain sm_80/90 features only) ----------------
__device__ __forceinline__ uint32_t smem_u32(const void* p) {
    uint32_t a;
    asm("{ .reg .u64 t; cvta.to.shared.u64 t, %1; cvt.u32.u64 %0, t; }" : "=r"(a) : "l"(p));
    return a;
}
__device__ __forceinline__ void cp16(uint32_t dst, const void* src) {
    asm volatile("cp.async.cg.shared.global [%0], [%1], 16;" :: "r"(dst), "l"(src) : "memory");
}
#define CP_COMMIT() asm volatile("cp.async.commit_group;" ::: "memory")
#define CP_WAIT1()  asm volatile("cp.async.wait_group 1;" ::: "memory")
#define CP_WAIT0()  asm volatile("cp.async.wait_group 0;" ::: "memory")
#define LDSM4(r, a) \
    asm volatile("ldmatrix.sync.aligned.m8n8.x4.shared.b16 {%0,%1,%2,%3}, [%4];" \
        : "=r"((r)[0]), "=r"((r)[1]), "=r"((r)[2]), "=r"((r)[3]) : "r"(a))
#define LDSM4T(r, a) \
    asm volatile("ldmatrix.sync.aligned.m8n8.x4.trans.shared.b16 {%0,%1,%2,%3}, [%4];" \
        : "=r"((r)[0]), "=r"((r)[1]), "=r"((r)[2]), "=r"((r)[3]) : "r"(a))
#define MMA_FP16(d, a, b0, b1) \
    asm volatile("mma.sync.aligned.m16n8k16.row.col.f32.f16.f16.f32 " \
        "{%0,%1,%2,%3}, {%4,%5,%6,%7}, {%8,%9}, {%0,%1,%2,%3};" \
        : "+f"((d)[0]), "+f"((d)[1]), "+f"((d)[2]), "+f"((d)[3]) \
        : "r"((a)[0]), "r"((a)[1]), "r"((a)[2]), "r"((a)[3]), "r"(b0), "r"(b1))

__device__ __forceinline__ uint32_t packh(float hi, float lo) {
    uint32_t d;
    asm("cvt.rn.f16x2.f32 %0, %1, %2;" : "=r"(d) : "f"(hi), "f"(lo));
    return d;
}

// smem row swizzle: 128B rows, 16B chunk q of row r at r*128 + ((q^(r&7))<<4)
#define SW(r, q) ((uint32_t)(r) * 128u + (uint32_t)((((q) ^ ((r) & 7)) << 4)))

// ---------------------------------------------------------------------------
// fused convert fp32 -> fp16 for x + 4 weights (one launch)
// ---------------------------------------------------------------------------
__global__ void __launch_bounds__(256) conv_all(
    const float* __restrict__ x,
    const float* __restrict__ Wq, const float* __restrict__ Wk,
    const float* __restrict__ Wv, const float* __restrict__ Wo,
    __half* __restrict__ xf, __half* __restrict__ wf)
{
    int blk = blockIdx.x;
    const float* src;
    __half* dst;
    int off;
    if (blk < 4096) {
        src = x; dst = xf; off = blk;
    } else {
        int w = (blk - 4096) >> 10;
        off = (blk - 4096) & 1023;
        src = (w == 0) ? Wq : (w == 1) ? Wk : (w == 2) ? Wv : Wo;
        dst = wf + (size_t)w * NW_;
    }
    int i = off * 1024 + threadIdx.x * 4;
    float4 v = *(const float4*)(src + i);
    *(uint32_t*)(dst + i)     = packh(v.y, v.x);
    *(uint32_t*)(dst + i + 2) = packh(v.w, v.z);
}

// ---------------------------------------------------------------------------
// fp16 GEMM core: BK=16, 4-stage cp.async ring (8KB/stage), fragment
// double-buffering (ldsm chunk c+1 while MMAing chunk c). CTA 128x128,
// 8 warps (4m x 2n), 2 CTAs/SM. One __syncthreads per iteration (bottom).
// Tail fix: once no further groups are issued (c >= 61), drain fully
// (wait_group 0) so the final chunks are guaranteed landed before ldsm.
// ---------------------------------------------------------------------------
#define ISSUE_G(slab) do { \
    uint32_t st_ = sbase + (uint32_t)(((slab) & 3) * 8192); \
    size_t go_ = (size_t)(slab) * 32; \
    cp16(st_ + 0    + sw_off, gA + go_); \
    cp16(st_ + 4096 + sw_off, gW + go_); \
    CP_COMMIT(); \
} while (0)

#define LOADFRAG(buf, slot) do { \
    uint32_t st_ = sbase + (uint32_t)((slot) * 8192); \
    LDSM4(Af[buf][0], st_ + aSw); \
    LDSM4(Af[buf][1], st_ + aSw + 512); \
    _Pragma("unroll") \
    for (int g4_ = 0; g4_ < 4; g4_++) \
        LDSM4(Bf[buf][g4_], st_ + 4096 + bSw + g4_ * 512); \
} while (0)

#define GEMM_BODY(Aptr, Wptr) \
    __shared__ __align__(128) char sm[4][8192]; \
    uint32_t sbase = smem_u32(sm); \
    int tid  = threadIdx.x; \
    int wid  = tid >> 5, lane = tid & 31; \
    int warp_m = wid & 3, warp_n = wid >> 2; \
    int lr = tid >> 1, lq = tid & 1; \
    uint32_t sw_off = (uint32_t)lr * 32 + (uint32_t)((lq ^ ((lr >> 2) & 1)) << 4); \
    const char* gA = (const char*)((Aptr) + (size_t)(bm + lr) * 1024) + lq * 16; \
    const char* gW = (const char*)((Wptr) + (size_t)(bn + lr) * 1024) + lq * 16; \
    int mat = lane >> 3, l7 = lane & 7; \
    int aR = warp_m * 32 + (mat & 1) * 8 + l7; \
    int aQ = mat >> 1; \
    int bR = warp_n * 64 + (mat >> 1) * 8 + l7; \
    int bQ = mat & 1; \
    uint32_t aSw = (uint32_t)aR * 32 + (uint32_t)((aQ ^ ((aR >> 2) & 1)) << 4); \
    uint32_t bSw = (uint32_t)bR * 32 + (uint32_t)((bQ ^ ((bR >> 2) & 1)) << 4); \
    float acc[2][8][4]; \
    _Pragma("unroll") \
    for (int mt = 0; mt < 2; mt++) \
        _Pragma("unroll") \
        for (int nt = 0; nt < 8; nt++) \
            _Pragma("unroll") \
            for (int j = 0; j < 4; j++) acc[mt][nt][j] = 0.f; \
    uint32_t Af[2][2][4], Bf[2][4][4]; \
    ISSUE_G(0); ISSUE_G(1); ISSUE_G(2); \
    CP_WAIT1();           /* chunks 0,1 landed */ \
    __syncthreads(); \
    LOADFRAG(0, 0); \
    int cur = 0; \
    for (int c = 0; c < 64; c++) { \
        if (c + 3 < 64) ISSUE_G(c + 3); \
        if (c + 1 < 64) LOADFRAG(cur ^ 1, (c + 1) & 3); \
        _Pragma("unroll") \
        for (int mt = 0; mt < 2; mt++) \
            _Pragma("unroll") \
            for (int nt = 0; nt < 8; nt++) \
                MMA_FP16(acc[mt][nt], Af[cur][mt], \
                         Bf[cur][nt >> 1][(nt & 1) * 2], Bf[cur][nt >> 1][(nt & 1) * 2 + 1]); \
        cur ^= 1; \
        if (c >= 60) CP_WAIT0(); else CP_WAIT1(); \
        __syncthreads();  /* visibility + WAR for slot (c+4)&3 */ \
    }

// ---------------------------------------------------------------------------
// Merged QKV GEMM: grid (24, 32), head-remap fp16 epilogue.
// ---------------------------------------------------------------------------
__global__ void __launch_bounds__(256, 2) tc_gemm_qkv(
    const __half* __restrict__ A, const __half* __restrict__ Wbase,
    const float* __restrict__ bq, const float* __restrict__ bk,
    const float* __restrict__ bv,
    __half* __restrict__ Qo, __half* __restrict__ Ko, __half* __restrict__ Vo)
{
    int bm = blockIdx.y * 128, bn = blockIdx.x * 128;   // bn in [0,3072)
    int which = bn >> 10;                               // 0=q 1=k 2=v
    const float* bias = (which == 0) ? bq : (which == 1) ? bk : bv;
    __half* Out = (which == 0) ? Qo : (which == 1) ? Ko : Vo;

    GEMM_BODY(A, Wbase)

    int g = lane >> 2, t = lane & 3;
#pragma unroll
    for (int mt = 0; mt < 2; mt++) {
        int row0 = bm + warp_m * 32 + mt * 16 + g;
#pragma unroll
        for (int nt = 0; nt < 8; nt++) {
            int col = bn + warp_n * 64 + nt * 8 + 2 * t;
            int inner = col & 1023;
            float2 bvv = *(const float2*)(bias + inner);
            float v0 = acc[mt][nt][0] + bvv.x, v1 = acc[mt][nt][1] + bvv.y;
            float v2 = acc[mt][nt][2] + bvv.x, v3 = acc[mt][nt][3] + bvv.y;
            int gph = inner >> 6, hd0 = inner & 63;
            int b0 = row0 >> 11, s0 = row0 & 2047;
            int b1 = (row0 + 8) >> 11, s1 = (row0 + 8) & 2047;
            size_t i0 = (size_t)(b0 * 16 + gph) * (S_ * HD_) + (size_t)s0 * HD_ + hd0;
            size_t i1 = (size_t)(b1 * 16 + gph) * (S_ * HD_) + (size_t)s1 * HD_ + hd0;
            *(uint32_t*)(Out + i0) = packh(v1, v0);
            *(uint32_t*)(Out + i1) = packh(v3, v2);
        }
    }
}

// ---------------------------------------------------------------------------
// Wo GEMM: grid (8, 32), fp32 row-major epilogue.
// ---------------------------------------------------------------------------
__global__ void __launch_bounds__(256, 2) tc_gemm_wo(
    const __half* __restrict__ A, const __half* __restrict__ W,
    const float* __restrict__ bias, float* __restrict__ C)
{
    int bm = blockIdx.y * 128, bn = blockIdx.x * 128;

    GEMM_BODY(A, W)

    int g = lane >> 2, t = lane & 3;
#pragma unroll
    for (int mt = 0; mt < 2; mt++) {
        int row0 = bm + warp_m * 32 + mt * 16 + g;
#pragma unroll
        for (int nt = 0; nt < 8; nt++) {
            int col = bn + warp_n * 64 + nt * 8 + 2 * t;
            float2 bvv = *(const float2*)(bias + col);
            *(float2*)(C + (size_t)row0 * H_ + col) =
                make_float2(acc[mt][nt][0] + bvv.x, acc[mt][nt][1] + bvv.y);
            *(float2*)(C + (size_t)(row0 + 8) * H_ + col) =
                make_float2(acc[mt][nt][2] + bvv.x, acc[mt][nt][3] + bvv.y);
        }
    }
}

// ---------------------------------------------------------------------------
// Single-term fp16 flash attention (exact R12 version; 2 CTAs/SM).
// ---------------------------------------------------------------------------
__global__ void __launch_bounds__(256, 2) attn_fp16(
    const __half* __restrict__ Qf, const __half* __restrict__ Kf,
    const __half* __restrict__ Vf, __half* __restrict__ Cf)
{
    extern __shared__ __align__(128) char smdyn[];   // 3 stages x 16KB
    uint32_t s0 = smem_u32(smdyn);

    int hidx = blockIdx.y, qt = blockIdx.x;
    int tid = threadIdx.x, warp = tid >> 5, lane = tid & 31;
    int g = lane >> 2, t = lane & 3;
    int mat = lane >> 3, l7 = lane & 7;

    size_t hoff = (size_t)hidx * (S_ * HD_);
    const char* Qg = (const char*)(Qf + hoff + (size_t)qt * 128 * HD_);
    const char* Kg = (const char*)(Kf + hoff);
    const char* Vg = (const char*)(Vf + hoff);

    {
        int r = tid >> 1, qb = (tid & 1) * 4;
#pragma unroll
        for (int i = 0; i < 4; i++)
            cp16(s0 + SW(r, qb + i), Qg + (size_t)r * 128 + (qb + i) * 16);
        CP_COMMIT();
        CP_WAIT0();
        __syncthreads();
    }
    uint32_t qf[4][4];
    {
        int aRow = warp * 16 + (mat & 1) * 8 + l7;
#pragma unroll
        for (int kc = 0; kc < 4; kc++) {
            int q = kc * 2 + (mat >> 1);
            LDSM4(qf[kc], s0 + SW(aRow, q));
        }
    }
    __syncthreads();

    int kr = tid >> 2, kqb = (tid & 3) * 2;
#define ISSUE_KV(kt) do { \
    uint32_t st_ = s0 + (uint32_t)(((kt) % 3) * 16384); \
    size_t ro_ = (size_t)((kt) * 64 + kr) * 128; \
    _Pragma("unroll") \
    for (int j_ = 0; j_ < 2; j_++) { \
        int q_ = kqb + j_; \
        uint32_t sw_ = SW(kr, q_); \
        cp16(st_ + 0    + sw_, Kg + ro_ + q_ * 16); \
        cp16(st_ + 8192 + sw_, Vg + ro_ + q_ * 16); \
    } \
    CP_COMMIT(); \
} while (0)

    float oacc[8][4];
#pragma unroll
    for (int j = 0; j < 8; j++)
#pragma unroll
        for (int i = 0; i < 4; i++) oacc[j][i] = 0.f;
    float m0 = -1e30f, m1 = -1e30f, l0 = 0.f, l1 = 0.f;
    const float SC = 0.18033688011112042f;   // (1/sqrt(64)) * log2(e)

    ISSUE_KV(0);
    ISSUE_KV(1);

    for (int kt = 0; kt < 32; kt++) {
        if (kt >= 30) CP_WAIT0(); else CP_WAIT1();
        __syncthreads();
        if (kt + 2 < 32) ISSUE_KV(kt + 2);
        uint32_t st = s0 + (uint32_t)((kt % 3) * 16384);

        float sacc[8][4];
#pragma unroll
        for (int j = 0; j < 8; j++)
#pragma unroll
            for (int i = 0; i < 4; i++) sacc[j][i] = 0.f;

#pragma unroll
        for (int nc = 0; nc < 4; nc++) {
            uint32_t kf[4][4];
            int bRow = nc * 16 + (mat >> 1) * 8 + l7;
#pragma unroll
            for (int kc = 0; kc < 4; kc++) {
                int q = kc * 2 + (mat & 1);
                LDSM4(kf[kc], st + SW(bRow, q));
            }
#pragma unroll
            for (int kc = 0; kc < 4; kc++) {
                MMA_FP16(sacc[2 * nc],     qf[kc], kf[kc][0], kf[kc][1]);
                MMA_FP16(sacc[2 * nc + 1], qf[kc], kf[kc][2], kf[kc][3]);
            }
        }

        float tm0 = -1e30f, tm1 = -1e30f;
#pragma unroll
        for (int j = 0; j < 8; j++) {
            tm0 = fmaxf(tm0, fmaxf(sacc[j][0], sacc[j][1]));
            tm1 = fmaxf(tm1, fmaxf(sacc[j][2], sacc[j][3]));
        }
        tm0 *= SC; tm1 *= SC;
        tm0 = fmaxf(tm0, __shfl_xor_sync(0xFFFFFFFFu, tm0, 1));
        tm0 = fmaxf(tm0, __shfl_xor_sync(0xFFFFFFFFu, tm0, 2));
        tm1 = fmaxf(tm1, __shfl_xor_sync(0xFFFFFFFFu, tm1, 1));
        tm1 = fmaxf(tm1, __shfl_xor_sync(0xFFFFFFFFu, tm1, 2));
        float nm0 = fmaxf(m0, tm0), nm1 = fmaxf(m1, tm1);
        float sc0 = exp2f(m0 - nm0), sc1 = exp2f(m1 - nm1);
        m0 = nm0; m1 = nm1;

        uint32_t pa[4][4];
        float sum0 = 0.f, sum1 = 0.f;
#pragma unroll
        for (int kc = 0; kc < 4; kc++) {
            int j0 = 2 * kc, j1 = 2 * kc + 1;
            float p00 = exp2f(sacc[j0][0] * SC - nm0);
            float p01 = exp2f(sacc[j0][1] * SC - nm0);
            float p02 = exp2f(sacc[j0][2] * SC - nm1);
            float p03 = exp2f(sacc[j0][3] * SC - nm1);
            float p10 = exp2f(sacc[j1][0] * SC - nm0);
            float p11 = exp2f(sacc[j1][1] * SC - nm0);
            float p12 = exp2f(sacc[j1][2] * SC - nm1);
            float p13 = exp2f(sacc[j1][3] * SC - nm1);
            sum0 += (p00 + p01) + (p10 + p11);
            sum1 += (p02 + p03) + (p12 + p13);
            pa[kc][0] = packh(p01, p00);
            pa[kc][1] = packh(p03, p02);
            pa[kc][2] = packh(p11, p10);
            pa[kc][3] = packh(p13, p12);
        }
        sum0 += __shfl_xor_sync(0xFFFFFFFFu, sum0, 1);
        sum0 += __shfl_xor_sync(0xFFFFFFFFu, sum0, 2);
        sum1 += __shfl_xor_sync(0xFFFFFFFFu, sum1, 1);
        sum1 += __shfl_xor_sync(0xFFFFFFFFu, sum1, 2);
        l0 = l0 * sc0 + sum0;
        l1 = l1 * sc1 + sum1;
#pragma unroll
        for (int j = 0; j < 8; j++) {
            oacc[j][0] *= sc0; oacc[j][1] *= sc0;
            oacc[j][2] *= sc1; oacc[j][3] *= sc1;
        }

#pragma unroll
        for (int nc2 = 0; nc2 < 4; nc2++) {
            uint32_t vf[4][4];
#pragma unroll
            for (int kc = 0; kc < 4; kc++) {
                int vRow = kc * 16 + (mat & 1) * 8 + l7;
                int q = nc2 * 2 + (mat >> 1);
                LDSM4T(vf[kc], st + 8192 + SW(vRow, q));
            }
#pragma unroll
            for (int kc = 0; kc < 4; kc++) {
                MMA_FP16(oacc[2 * nc2],     pa[kc], vf[kc][0], vf[kc][1]);
                MMA_FP16(oacc[2 * nc2 + 1], pa[kc], vf[kc][2], vf[kc][3]);
            }
        }
    }
#undef ISSUE_KV

    float inv0 = 1.f / l0, inv1 = 1.f / l1;
    int b  = hidx >> 4, gh = hidx & 15;
    int srow = qt * 128 + warp * 16 + g;
    size_t base0 = ((size_t)b * S_ + srow) * H_ + gh * 64 + 2 * t;
    size_t base1 = base0 + 8 * (size_t)H_;
#pragma unroll
    for (int j = 0; j < 8; j++) {
        float v0 = oacc[j][0] * inv0, v1 = oacc[j][1] * inv0;
        float v2 = oacc[j][2] * inv1, v3 = oacc[j][3] * inv1;
        *(uint32_t*)(Cf + base0 + j * 8) = packh(v1, v0);
        *(uint32_t*)(Cf + base1 + j * 8) = packh(v3, v2);
    }
}

// ---------------------------------------------------------------------------
extern "C" void kernel_launch(void* const* d_in, const int* in_sizes, int n_in,
                              void* d_out, int out_size)
{
    const float* x  = (const float*)d_in[0];
    const float* Wq = (const float*)d_in[1];
    const float* bq = (const float*)d_in[2];
    const float* Wk = (const float*)d_in[3];
    const float* bk = (const float*)d_in[4];
    const float* Wv = (const float*)d_in[5];
    const float* bv = (const float*)d_in[6];
    const float* Wo = (const float*)d_in[7];
    const float* bo = (const float*)d_in[8];
    float* out = (float*)d_out;

    __half *xf, *wf, *cf, *qf, *kf, *vf;
    cudaGetSymbolAddress((void**)&xf, g_xf);
    cudaGetSymbolAddress((void**)&wf, g_wf);
    cudaGetSymbolAddress((void**)&cf, g_cf);
    cudaGetSymbolAddress((void**)&qf, g_qf);
    cudaGetSymbolAddress((void**)&kf, g_kf);
    cudaGetSymbolAddress((void**)&vf, g_vf);

    cudaFuncSetAttribute(attn_fp16, cudaFuncAttributeMaxDynamicSharedMemorySize, 49152);

    conv_all<<<8192, 256>>>(x, Wq, Wk, Wv, Wo, xf, wf);

    tc_gemm_qkv<<<dim3(24, 32), 256>>>(xf, wf, bq, bk, bv, qf, kf, vf);

    attn_fp16<<<dim3(16, 32), 256, 49152>>>(qf, kf, vf, cf);

    tc_gemm_wo<<<dim3(8, 32), 256>>>(cf, wf + 3 * NW_, bo, out);
}